// round 10
// baseline (speedup 1.0000x reference)
#include <cuda_runtime.h>
#include <cstddef>

// Problem constants (fixed by the dataset)
#define TBL 32      // T
#define DIM 64      // D
#define GRP 1024    // bags per table value = num_bags / TBL
#define RSTRIDE (TBL * DIM / 4)   // float4 stride between consecutive rows e

// One warp per bag, float4 layout: 16 lanes cover one 256B row; the two
// half-warps fetch DIFFERENT rows in the same LDG.128 instruction.
// Main loop: 5 LDG.128 = 10 rows per iteration; L=50 fits exactly (no tail).
// Next iteration's indices are prefetched before the current accumulate so
// the idx->gather serial chain never sits on the critical path.
// Bags are table-grouped so bags sharing table slice W[:, t, :] run
// temporally adjacent and repeated indices become L2 hits.
// End: halves combined with 4x shfl.xor(16), half-warp streaming store.
__global__ void __launch_bounds__(256, 7)
embbag_kernel(const float* __restrict__ W,
              const int*   __restrict__ feat,
              const int*   __restrict__ off,
              float*       __restrict__ out,
              int num_bags)
{
    int gwarp = (blockIdx.x * blockDim.x + threadIdx.x) >> 5;
    int lane  = threadIdx.x & 31;
    if (gwarp >= num_bags) return;

    // Table-grouped schedule: warps [t*GRP, (t+1)*GRP) handle table t.
    const int table = gwarp >> 10;           // g / 1024
    const int group = gwarp & (GRP - 1);     // g % 1024
    const int bag   = (group << 5) + table;  // original bag id; bag % 32 == table

    const int start = off[bag];
    const int end   = off[bag + 1];

    const int half = lane >> 4;              // which row of the pair
    const int hl   = lane & 15;              // float4 slot within the row

    // Row e lives at float4 index (e*TBL + table)*16 + hl.
    const float4* Wq = (const float4*)W + (size_t)table * (DIM / 4) + hl;

    float4 acc = make_float4(0.f, 0.f, 0.f, 0.f);

    int j = start;
    int nfull = (end - start) / 10;          // full 10-row batches (5 for L=50)

    if (nfull > 0) {
        // Prologue: indices for batch 0.
        int e0 = __ldcs(feat + j + 0 + half);
        int e1 = __ldcs(feat + j + 2 + half);
        int e2 = __ldcs(feat + j + 4 + half);
        int e3 = __ldcs(feat + j + 6 + half);
        int e4 = __ldcs(feat + j + 8 + half);

        for (int b = 0; b < nfull; ++b) {
            // Issue the 5 independent row-gathers for this batch.
            float4 v0 = __ldg(Wq + (size_t)e0 * RSTRIDE);
            float4 v1 = __ldg(Wq + (size_t)e1 * RSTRIDE);
            float4 v2 = __ldg(Wq + (size_t)e2 * RSTRIDE);
            float4 v3 = __ldg(Wq + (size_t)e3 * RSTRIDE);
            float4 v4 = __ldg(Wq + (size_t)e4 * RSTRIDE);

            // Prefetch next batch's indices while gathers are in flight.
            j += 10;
            if (b + 1 < nfull) {
                e0 = __ldcs(feat + j + 0 + half);
                e1 = __ldcs(feat + j + 2 + half);
                e2 = __ldcs(feat + j + 4 + half);
                e3 = __ldcs(feat + j + 6 + half);
                e4 = __ldcs(feat + j + 8 + half);
            }

            acc.x += ((v0.x + v1.x) + (v2.x + v3.x)) + v4.x;
            acc.y += ((v0.y + v1.y) + (v2.y + v3.y)) + v4.y;
            acc.z += ((v0.z + v1.z) + (v2.z + v3.z)) + v4.z;
            acc.w += ((v0.w + v1.w) + (v2.w + v3.w)) + v4.w;
        }
    }

    // Pair tail (L % 10 != 0 generality; never taken for L=50).
    for (; j + 2 <= end; j += 2) {
        int e = __ldcs(feat + j + half);
        float4 v = __ldg(Wq + (size_t)e * RSTRIDE);
        acc.x += v.x; acc.y += v.y; acc.z += v.z; acc.w += v.w;
    }
    // Single-row tail (only half 0 contributes).
    if (j < end) {
        int e = __ldcs(feat + j);
        if (half == 0) {
            float4 v = __ldg(Wq + (size_t)e * RSTRIDE);
            acc.x += v.x; acc.y += v.y; acc.z += v.z; acc.w += v.w;
        }
    }

    // Combine the two half-warp partial sums (same dims, different rows).
    acc.x += __shfl_xor_sync(0xFFFFFFFFu, acc.x, 16);
    acc.y += __shfl_xor_sync(0xFFFFFFFFu, acc.y, 16);
    acc.z += __shfl_xor_sync(0xFFFFFFFFu, acc.z, 16);
    acc.w += __shfl_xor_sync(0xFFFFFFFFu, acc.w, 16);

    // Half-warp streaming store: 16 lanes x float4 = 256B row, coalesced.
    if (half == 0) {
        float4* o = (float4*)(out + (size_t)bag * DIM) + hl;
        __stcs(o, acc);
    }
}

extern "C" void kernel_launch(void* const* d_in, const int* in_sizes, int n_in,
                              void* d_out, int out_size)
{
    const float* W    = (const float*)d_in[0];   // (E, T, D) fp32
    const int*   feat = (const int*)d_in[1];     // (B*T*L,) int32
    const int*   off  = (const int*)d_in[2];     // (B*T+1,) int32

    int num_bags = in_sizes[2] - 1;              // B*T = 32768
    float* out = (float*)d_out;                  // (B, T, D) fp32

    int threads = 256;                           // 8 warps = 8 bags per block
    int total_threads = num_bags * 32;
    int blocks = (total_threads + threads - 1) / threads;

    embbag_kernel<<<blocks, threads>>>(W, feat, off, out, num_bags);
}

// round 13
// speedup vs baseline: 1.4610x; 1.4610x over previous
#include <cuda_runtime.h>
#include <cstddef>
#include <cstdint>

// Problem constants (fixed by the dataset)
#define TBL 32      // T
#define DIM 64      // D
#define GRP 1024    // bags per table value = num_bags / TBL

#define DEPTH       8                    // pipeline stages in flight (2 rows/stage)
#define STAGE_BYTES 512                  // 2 rows * 256B
#define WARP_SMEM   (DEPTH * STAGE_BYTES)// 4KB ring per warp
#define ROW_BYTES   (TBL * DIM * 4)      // 8192B between consecutive row ids e

// One warp per bag. cp.async (LDGSTS) stages gathered rows into a per-warp
// smem ring, so in-flight gather depth is bounded by smem (16 rows/warp),
// not registers. Each lane copies and later reads back exactly its own 16B
// of a row -> warp-private, no barriers; cp.async group accounting is the
// only ordering. Ring discipline: consume stage s BEFORE issuing stage
// s+DEPTH into the same slot (fixes the R10 overwrite hazard).
// Indices are preloaded (2 regs/lane) and distributed via shfl, removing
// index loads from the issue path entirely.
// Bags are table-grouped so bags sharing table slice W[:, t, :] run
// temporally adjacent and repeated indices become L2 hits.
__global__ void __launch_bounds__(256)
embbag_kernel(const float* __restrict__ W,
              const int*   __restrict__ feat,
              const int*   __restrict__ off,
              float*       __restrict__ out,
              int num_bags)
{
    __shared__ char ring[8 * WARP_SMEM];   // 32KB static, 8 warps/block

    const int tid  = threadIdx.x;
    const int wid  = tid >> 5;
    const int lane = tid & 31;
    const int gwarp = (blockIdx.x * blockDim.x + tid) >> 5;
    if (gwarp >= num_bags) return;

    // Table-grouped schedule: warps [t*GRP, (t+1)*GRP) handle table t.
    const int table = gwarp >> 10;           // g / 1024
    const int group = gwarp & (GRP - 1);     // g % 1024
    const int bag   = (group << 5) + table;  // bag % 32 == table

    const int start = off[bag];
    const int end   = off[bag + 1];
    const int cnt   = end - start;

    const int half = lane >> 4;              // which row of the pair
    const int hl   = lane & 15;              // 16B slot within the row

    // Preload this bag's indices cooperatively (covers cnt <= 64).
    int i0 = (lane      < cnt) ? __ldcs(feat + start + lane)      : 0;
    int i1 = (32 + lane < cnt) ? __ldcs(feat + start + 32 + lane) : 0;

    // Global byte base of this lane's 16B within a row of its table slice.
    const char* Wb = (const char*)W + (size_t)table * 256 + (size_t)hl * 16;

    const uint32_t sbase =
        (uint32_t)__cvta_generic_to_shared(ring + wid * WARP_SMEM) +
        (uint32_t)lane * 16;

    float4 acc = make_float4(0.f, 0.f, 0.f, 0.f);

    const int nstages = cnt >> 1;            // row pairs (25 for L=50)

    // idx for stage s, this lane's half: feat[start + 2s + half]
    #define GET_IDX(s, e_out) do {                                          \
        int _src = 2 * (s) + half;                                          \
        int _a = __shfl_sync(0xFFFFFFFFu, i0, _src & 31);                   \
        int _b = __shfl_sync(0xFFFFFFFFu, i1, (_src - 32) & 31);            \
        (e_out) = (_src < 32) ? _a : _b;                                    \
    } while (0)

    #define ISSUE(s) do {                                                   \
        int _e; GET_IDX(s, _e);                                             \
        const char* _src = Wb + (size_t)_e * ROW_BYTES;                     \
        uint32_t _dst = sbase + (uint32_t)((s) & (DEPTH - 1)) * STAGE_BYTES;\
        asm volatile("cp.async.cg.shared.global [%0], [%1], 16;\n"          \
                     :: "r"(_dst), "l"(_src) : "memory");                   \
    } while (0)

    #define CONSUME(s) do {                                                 \
        float4 _v;                                                          \
        uint32_t _a = sbase + (uint32_t)((s) & (DEPTH - 1)) * STAGE_BYTES;  \
        asm volatile("ld.shared.v4.f32 {%0,%1,%2,%3}, [%4];\n"              \
                     : "=f"(_v.x), "=f"(_v.y), "=f"(_v.z), "=f"(_v.w)       \
                     : "r"(_a));                                            \
        acc.x += _v.x; acc.y += _v.y; acc.z += _v.z; acc.w += _v.w;         \
    } while (0)

    if (nstages >= DEPTH) {
        // Prologue: fill all DEPTH ring slots, one commit group per stage.
        for (int s = 0; s < DEPTH; ++s) {
            ISSUE(s);
            asm volatile("cp.async.commit_group;\n" ::: "memory");
        }
        // Steady state: wait until stage s complete (commits so far =
        // DEPTH + s, so pending <= DEPTH-1 implies stages <= s are done),
        // consume slot, THEN refill it with stage s+DEPTH. Empty commits
        // in the tail keep group accounting uniform.
        for (int s = 0; s < nstages; ++s) {
            asm volatile("cp.async.wait_group %0;\n" :: "n"(DEPTH - 1) : "memory");
            CONSUME(s);
            if (s + DEPTH < nstages) ISSUE(s + DEPTH);
            asm volatile("cp.async.commit_group;\n" ::: "memory");
        }
    } else if (nstages > 0) {
        // Short-bag path: issue all, wait all, consume.
        for (int s = 0; s < nstages; ++s) {
            ISSUE(s);
            asm volatile("cp.async.commit_group;\n" ::: "memory");
        }
        asm volatile("cp.async.wait_group 0;\n" ::: "memory");
        for (int s = 0; s < nstages; ++s) {
            CONSUME(s);
        }
    }

    // Odd single-row tail (half 0 only; not taken for L=50).
    if (cnt & 1) {
        int src = cnt - 1;
        int a0 = __shfl_sync(0xFFFFFFFFu, i0, src & 31);
        int b0 = __shfl_sync(0xFFFFFFFFu, i1, (src - 32) & 31);
        int e = (src < 32) ? a0 : b0;
        if (half == 0) {
            float4 v = __ldg((const float4*)(Wb + (size_t)e * ROW_BYTES));
            acc.x += v.x; acc.y += v.y; acc.z += v.z; acc.w += v.w;
        }
    }

    // Combine the two half-warp partial sums (same dims, different rows).
    acc.x += __shfl_xor_sync(0xFFFFFFFFu, acc.x, 16);
    acc.y += __shfl_xor_sync(0xFFFFFFFFu, acc.y, 16);
    acc.z += __shfl_xor_sync(0xFFFFFFFFu, acc.z, 16);
    acc.w += __shfl_xor_sync(0xFFFFFFFFu, acc.w, 16);

    // Half-warp streaming store: 16 lanes x float4 = 256B row, coalesced.
    if (half == 0) {
        float4* o = (float4*)(out + (size_t)bag * DIM) + hl;
        __stcs(o, acc);
    }

    #undef CONSUME
    #undef ISSUE
    #undef GET_IDX
}

extern "C" void kernel_launch(void* const* d_in, const int* in_sizes, int n_in,
                              void* d_out, int out_size)
{
    const float* W    = (const float*)d_in[0];   // (E, T, D) fp32
    const int*   feat = (const int*)d_in[1];     // (B*T*L,) int32
    const int*   off  = (const int*)d_in[2];     // (B*T+1,) int32

    int num_bags = in_sizes[2] - 1;              // B*T = 32768
    float* out = (float*)d_out;                  // (B, T, D) fp32

    int threads = 256;                           // 8 warps = 8 bags per block
    int total_threads = num_bags * 32;
    int blocks = (total_threads + threads - 1) / threads;

    embbag_kernel<<<blocks, threads>>>(W, feat, off, out, num_bags);
}